// round 7
// baseline (speedup 1.0000x reference)
#include <cuda_runtime.h>
#include <cuda_fp16.h>
#include <stdint.h>

#define NSAMP 8192
#define NCENT 10000
#define XDIM  1024
#define YDIM  128
#define NCHUNKS 79

// ---------------- device scratch ----------------
__device__ __align__(16) __half g_xt[(size_t)64 * 16 * 8192];       // 16 MB
__device__ __align__(16) __half g_zt[(size_t)NCHUNKS * 16 * 8192];  // ~20 MB
__device__ __align__(16) __half g_wt[(size_t)NCHUNKS * 16384];      // 2.5 MB
__device__ float g_xsq[NSAMP];
__device__ float g_zsq[NCHUNKS * 128];
__device__ float g_part[(size_t)2 * NSAMP * YDIM];

// smem: 4 stages x 32KB (X 16KB | Z 16KB), W 2x32KB, K 32KB, zsq 2x512B
static constexpr int OFF_W  = 131072;
static constexpr int OFF_K  = 196608;
static constexpr int OFF_ZQ = 229376;
static constexpr int SMEM_TOTAL = 230400;

// ---------------- helpers ----------------
__device__ __forceinline__ uint32_t smem_u32(const void* p) {
    uint32_t a;
    asm("{ .reg .u64 t; cvta.to.shared.u64 t, %1; cvt.u32.u64 %0, t; }" : "=r"(a) : "l"(p));
    return a;
}
#define CP_ASYNC16(dst, src) \
    asm volatile("cp.async.cg.shared.global [%0], [%1], 16;" :: "r"(dst), "l"(src) : "memory")
#define CP_COMMIT() asm volatile("cp.async.commit_group;" ::: "memory")
template <int N> __device__ __forceinline__ void cp_wait() {
    asm volatile("cp.async.wait_group %0;" :: "n"(N) : "memory");
}

__device__ __forceinline__ uint32_t tile_off(int r, int c) {
    return (uint32_t)(r * 128 + (((c >> 3) ^ (r & 7)) << 4) + ((c & 7) << 1));
}
__device__ __forceinline__ uint32_t lds_addr(uint32_t base, int r0, int c8b, int lane) {
    int r = r0 + (lane & 15);
    int c8 = c8b + ((lane >> 4) & 1);
    return base + r * 128 + ((c8 ^ (r & 7)) << 4);
}
__device__ __forceinline__ void ldsm4(uint32_t a, uint32_t& r0, uint32_t& r1, uint32_t& r2, uint32_t& r3) {
    asm volatile("ldmatrix.sync.aligned.m8n8.x4.shared.b16 {%0,%1,%2,%3}, [%4];"
                 : "=r"(r0), "=r"(r1), "=r"(r2), "=r"(r3) : "r"(a));
}
__device__ __forceinline__ void ldsm4t(uint32_t a, uint32_t& r0, uint32_t& r1, uint32_t& r2, uint32_t& r3) {
    asm volatile("ldmatrix.sync.aligned.m8n8.x4.trans.shared.b16 {%0,%1,%2,%3}, [%4];"
                 : "=r"(r0), "=r"(r1), "=r"(r2), "=r"(r3) : "r"(a));
}
__device__ __forceinline__ void mma16816(float* c, const uint32_t* a, const uint32_t* b) {
    asm volatile("mma.sync.aligned.m16n8k16.row.col.f32.f16.f16.f32 "
        "{%0,%1,%2,%3}, {%4,%5,%6,%7}, {%8,%9}, {%0,%1,%2,%3};"
        : "+f"(c[0]), "+f"(c[1]), "+f"(c[2]), "+f"(c[3])
        : "r"(a[0]), "r"(a[1]), "r"(a[2]), "r"(a[3]), "r"(b[0]), "r"(b[1]));
}

// ---------------- prep kernels ----------------
__global__ void prep_xz_all(const float* __restrict__ x, const float* __restrict__ z) {
    int blk = blockIdx.x, ks = blockIdx.y, t = threadIdx.x;
    const float* src;
    __half* d;
    int validRows, lblk;
    if (blk < 64) { src = x; d = g_xt; validRows = NSAMP; lblk = blk; }
    else          { src = z; d = g_zt; validRows = NCENT; lblk = blk - 64; }
    d += ((size_t)(lblk * 16 + ks)) * 8192;
    #pragma unroll
    for (int it = 0; it < 4; ++it) {
        int id = it * 256 + t;
        int r = id >> 3, c8 = id & 7;
        int gr = lblk * 128 + r;
        float4 v0 = {0, 0, 0, 0}, v1 = {0, 0, 0, 0};
        if (gr < validRows) {
            const float* p = src + (size_t)gr * XDIM + ks * 64 + c8 * 8;
            v0 = *(const float4*)p;
            v1 = *(const float4*)(p + 4);
        }
        __half2* o = (__half2*)((char*)d + r * 128 + ((c8 ^ (r & 7)) << 4));
        o[0] = __floats2half2_rn(v0.x, v0.y);
        o[1] = __floats2half2_rn(v0.z, v0.w);
        o[2] = __floats2half2_rn(v1.x, v1.y);
        o[3] = __floats2half2_rn(v1.z, v1.w);
    }
}
__global__ void prep_w(const float* __restrict__ w) {
    int chunk = blockIdx.x, sub = blockIdx.y, t = threadIdx.x;
    __half* d = g_wt + (size_t)chunk * 16384 + sub * 8192;
    #pragma unroll
    for (int it = 0; it < 4; ++it) {
        int id = it * 256 + t;
        int r = id >> 3, c8 = id & 7;
        int center = chunk * 128 + r;
        float4 v0 = {0, 0, 0, 0}, v1 = {0, 0, 0, 0};
        if (center < NCENT) {
            const float* p = w + (size_t)center * YDIM + sub * 64 + c8 * 8;
            v0 = *(const float4*)p;
            v1 = *(const float4*)(p + 4);
        }
        __half2* o = (__half2*)((char*)d + r * 128 + ((c8 ^ (r & 7)) << 4));
        o[0] = __floats2half2_rn(v0.x, v0.y);
        o[1] = __floats2half2_rn(v0.z, v0.w);
        o[2] = __floats2half2_rn(v1.x, v1.y);
        o[3] = __floats2half2_rn(v1.z, v1.w);
    }
}
__global__ void prep_sq(const float* __restrict__ x, const float* __restrict__ z) {
    __shared__ float ws[4];
    int r = blockIdx.x, t = threadIdx.x;
    const float* src = nullptr;
    float* dst;
    if (r < NSAMP) { src = x + (size_t)r * XDIM; dst = g_xsq + r; }
    else {
        int zr = r - NSAMP;
        dst = g_zsq + zr;
        if (zr < NCENT) src = z + (size_t)zr * XDIM;
    }
    float s = 0.f;
    if (src) {
        float4 a = ((const float4*)src)[t];
        float4 b = ((const float4*)src)[t + 128];
        s = a.x * a.x;
        s = fmaf(a.y, a.y, s); s = fmaf(a.z, a.z, s); s = fmaf(a.w, a.w, s);
        s = fmaf(b.x, b.x, s); s = fmaf(b.y, b.y, s);
        s = fmaf(b.z, b.z, s); s = fmaf(b.w, b.w, s);
    }
    for (int o = 16; o; o >>= 1) s += __shfl_down_sync(0xffffffffu, s, o);
    if ((t & 31) == 0) ws[t >> 5] = s;
    __syncthreads();
    if (t == 0) dst[0] = ws[0] + ws[1] + ws[2] + ws[3];
}
__global__ void reduce2(float* __restrict__ out) {
    int i = blockIdx.x * 128 + threadIdx.x;
    const float4* p = (const float4*)g_part;
    float4 a = p[i], b = p[i + (NSAMP * YDIM) / 4];
    ((float4*)out)[i] = make_float4(a.x + b.x, a.y + b.y, a.z + b.z, a.w + b.w);
}

// ---------------- main kernel (256 threads, 8 warps 2x4, frag double-buffer) ----
__device__ __forceinline__ void load_stage(uint32_t sb, int s, const char* x, const char* z, int tid) {
    uint32_t dst = sb + s * 32768;
    #pragma unroll
    for (int i = 0; i < 4; ++i) CP_ASYNC16(dst + (i * 256 + tid) * 16, x + (i * 256 + tid) * 16);
    #pragma unroll
    for (int i = 0; i < 4; ++i) CP_ASYNC16(dst + 16384 + (i * 256 + tid) * 16, z + (i * 256 + tid) * 16);
    CP_COMMIT();
}
__device__ __forceinline__ void load_wq(uint32_t sb, int c, int tid) {
    const char* wg = (const char*)(g_wt + (size_t)c * 16384);
    uint32_t wdst = sb + OFF_W + (uint32_t)(c & 1) * 32768;
    #pragma unroll
    for (int i = 0; i < 8; ++i) CP_ASYNC16(wdst + (i * 256 + tid) * 16, wg + (i * 256 + tid) * 16);
    if (tid < 32)
        CP_ASYNC16(sb + OFF_ZQ + (uint32_t)(c & 1) * 512 + tid * 16,
                   (const char*)(g_zsq + c * 128) + tid * 16);
    CP_COMMIT();
}

__global__ __launch_bounds__(256, 1) void laplace_main() {
    extern __shared__ char smem[];
    const int tid = threadIdx.x, lane = tid & 31, wid = tid >> 5;
    const int wm = wid >> 2, wn = wid & 3;          // 2 x 4 warp grid, warp tile 64x32
    const int gid = lane >> 2, tig = lane & 3;
    const int mblk = blockIdx.x, grp = blockIdx.y;
    const int c0 = grp ? 40 : 0, c1 = grp ? NCHUNKS : 40;

    uint32_t sb = smem_u32(smem);

    float xsq[8];
    #pragma unroll
    for (int i = 0; i < 4; ++i) {
        xsq[2 * i]     = g_xsq[mblk * 128 + wm * 64 + i * 16 + gid];
        xsq[2 * i + 1] = g_xsq[mblk * 128 + wm * 64 + i * 16 + gid + 8];
    }

    float O[4][4][4];
    #pragma unroll
    for (int i = 0; i < 4; ++i)
        #pragma unroll
        for (int j = 0; j < 4; ++j)
            O[i][j][0] = O[i][j][1] = O[i][j][2] = O[i][j][3] = 0.f;

    const char* xg = (const char*)(g_xt + (size_t)mblk * 16 * 8192);

    // fragment double buffers
    uint32_t a[2][4][4], b[2][4][2];

    // prologue: stages 0-2 + W/zsq of first chunk
    {
        const char* zg = (const char*)(g_zt + (size_t)c0 * 16 * 8192);
        #pragma unroll
        for (int p = 0; p < 3; ++p) load_stage(sb, p, xg + p * 16384, zg + p * 16384, tid);
        load_wq(sb, c0, tid);
    }

    for (int c = c0; c < c1; ++c) {
        const char* zg = (const char*)(g_zt + (size_t)c * 16 * 8192);

        float S[4][4][4];
        #pragma unroll
        for (int i = 0; i < 4; ++i)
            #pragma unroll
            for (int j = 0; j < 4; ++j)
                S[i][j][0] = S[i][j][1] = S[i][j][2] = S[i][j][3] = 0.f;

        for (int ks = 0; ks < 16; ++ks) {
            int s = ks & 3;
            if (ks < 3) cp_wait<3>();
            else if (ks <= 13) cp_wait<2>();
            else if (ks == 14) cp_wait<1>();
            else cp_wait<0>();
            __syncthreads();
            if (ks <= 12) load_stage(sb, (ks + 3) & 3, xg + (ks + 3) * 16384, zg + (ks + 3) * 16384, tid);

            uint32_t xb = sb + s * 32768, zb = xb + 16384;
            // preload k16=0 fragments into buffer 0
            #pragma unroll
            for (int i = 0; i < 4; ++i)
                ldsm4(lds_addr(xb, wm * 64 + i * 16, 0, lane),
                      a[0][i][0], a[0][i][1], a[0][i][2], a[0][i][3]);
            #pragma unroll
            for (int jj = 0; jj < 2; ++jj) {
                uint32_t r0, r1, r2, r3;
                ldsm4(lds_addr(zb, wn * 32 + jj * 16, 0, lane), r0, r1, r2, r3);
                b[0][2 * jj][0] = r0; b[0][2 * jj][1] = r2;
                b[0][2 * jj + 1][0] = r1; b[0][2 * jj + 1][1] = r3;
            }
            #pragma unroll
            for (int k16 = 0; k16 < 4; ++k16) {
                const int q = k16 & 1, nq = q ^ 1;
                if (k16 < 3) {   // prefetch next k16 frags while MMAs run
                    #pragma unroll
                    for (int i = 0; i < 4; ++i)
                        ldsm4(lds_addr(xb, wm * 64 + i * 16, (k16 + 1) * 2, lane),
                              a[nq][i][0], a[nq][i][1], a[nq][i][2], a[nq][i][3]);
                    #pragma unroll
                    for (int jj = 0; jj < 2; ++jj) {
                        uint32_t r0, r1, r2, r3;
                        ldsm4(lds_addr(zb, wn * 32 + jj * 16, (k16 + 1) * 2, lane), r0, r1, r2, r3);
                        b[nq][2 * jj][0] = r0; b[nq][2 * jj][1] = r2;
                        b[nq][2 * jj + 1][0] = r1; b[nq][2 * jj + 1][1] = r3;
                    }
                }
                #pragma unroll
                for (int i = 0; i < 4; ++i)
                    #pragma unroll
                    for (int j = 0; j < 4; ++j)
                        mma16816(S[i][j], a[q][i], b[q][j]);
            }
        }
        __syncthreads();   // all ldsm of this chunk done -> stages reusable

        // prefetch next chunk (overlaps epilogue + GEMM2)
        if (c + 1 < c1) {
            const char* zg2 = (const char*)(g_zt + (size_t)(c + 1) * 16 * 8192);
            #pragma unroll
            for (int p = 0; p < 3; ++p) load_stage(sb, p, xg + p * 16384, zg2 + p * 16384, tid);
            load_wq(sb, c + 1, tid);
        }

        // epilogue: S -> k (fp16) -> smem K tile [m][center]
        const float* zqs = (const float*)(smem + OFF_ZQ + (c & 1) * 512);
        char* kbase = smem + OFF_K + (wn >> 1) * 16384;
        #pragma unroll
        for (int j = 0; j < 4; ++j) {
            int col = wn * 32 + j * 8 + 2 * tig;
            float zq0 = zqs[col], zq1 = zqs[col + 1];
            #pragma unroll
            for (int i = 0; i < 4; ++i) {
                int r = wm * 64 + i * 16 + gid;
                float d2a = fmaxf(fmaf(-2.f, S[i][j][0], xsq[2 * i] + zq0), 1e-12f);
                float d2b = fmaxf(fmaf(-2.f, S[i][j][1], xsq[2 * i] + zq1), 1e-12f);
                float d2c = fmaxf(fmaf(-2.f, S[i][j][2], xsq[2 * i + 1] + zq0), 1e-12f);
                float d2d = fmaxf(fmaf(-2.f, S[i][j][3], xsq[2 * i + 1] + zq1), 1e-12f);
                float k0 = __expf(-0.1f * d2a * __frsqrt_rn(d2a));
                float k1 = __expf(-0.1f * d2b * __frsqrt_rn(d2b));
                float k2 = __expf(-0.1f * d2c * __frsqrt_rn(d2c));
                float k3 = __expf(-0.1f * d2d * __frsqrt_rn(d2d));
                *(__half2*)(kbase + tile_off(r, col & 63))     = __floats2half2_rn(k0, k1);
                *(__half2*)(kbase + tile_off(r + 8, col & 63)) = __floats2half2_rn(k2, k3);
            }
        }
        __syncthreads();

        // GEMM2: O += K[m][center] * W[center][y]  (frag double-buffered)
        uint32_t wbase = sb + OFF_W + (uint32_t)(c & 1) * 32768 + (wn >> 1) * 16384;
        // preload k0=0
        #pragma unroll
        for (int i = 0; i < 4; ++i)
            ldsm4(lds_addr(sb + OFF_K, wm * 64 + i * 16, 0, lane),
                  a[0][i][0], a[0][i][1], a[0][i][2], a[0][i][3]);
        #pragma unroll
        for (int jj = 0; jj < 2; ++jj) {
            uint32_t r0, r1, r2, r3;
            ldsm4t(lds_addr(wbase, 0, (wn & 1) * 4 + jj * 2, lane), r0, r1, r2, r3);
            b[0][2 * jj][0] = r0; b[0][2 * jj][1] = r1;
            b[0][2 * jj + 1][0] = r2; b[0][2 * jj + 1][1] = r3;
        }
        #pragma unroll
        for (int k0 = 0; k0 < 8; ++k0) {
            const int q = k0 & 1, nq = q ^ 1;
            if (k0 < 7) {
                int kn = k0 + 1;
                #pragma unroll
                for (int i = 0; i < 4; ++i)
                    ldsm4(lds_addr(sb + OFF_K + (kn >> 2) * 16384, wm * 64 + i * 16, (kn & 3) * 2, lane),
                          a[nq][i][0], a[nq][i][1], a[nq][i][2], a[nq][i][3]);
                #pragma unroll
                for (int jj = 0; jj < 2; ++jj) {
                    uint32_t r0, r1, r2, r3;
                    ldsm4t(lds_addr(wbase, kn * 16, (wn & 1) * 4 + jj * 2, lane), r0, r1, r2, r3);
                    b[nq][2 * jj][0] = r0; b[nq][2 * jj][1] = r1;
                    b[nq][2 * jj + 1][0] = r2; b[nq][2 * jj + 1][1] = r3;
                }
            }
            #pragma unroll
            for (int i = 0; i < 4; ++i)
                #pragma unroll
                for (int j = 0; j < 4; ++j)
                    mma16816(O[i][j], a[q][i], b[q][j]);
        }
        // no trailing sync: next write to K is gated by the per-ks syncs of next chunk
    }

    // writeout partials
    float* pout = g_part + (size_t)grp * NSAMP * YDIM;
    #pragma unroll
    for (int i = 0; i < 4; ++i)
        #pragma unroll
        for (int j = 0; j < 4; ++j) {
            int r = mblk * 128 + wm * 64 + i * 16 + gid;
            int col = wn * 32 + j * 8 + 2 * tig;
            *(float2*)&pout[(size_t)r * YDIM + col] = make_float2(O[i][j][0], O[i][j][1]);
            *(float2*)&pout[(size_t)(r + 8) * YDIM + col] = make_float2(O[i][j][2], O[i][j][3]);
        }
}

// ---------------- launch ----------------
extern "C" void kernel_launch(void* const* d_in, const int* in_sizes, int n_in,
                              void* d_out, int out_size) {
    const float* samples = (const float*)d_in[0];
    const float* centers = (const float*)d_in[1];
    const float* weight  = (const float*)d_in[2];
    float* out = (float*)d_out;

    cudaFuncSetAttribute(laplace_main, cudaFuncAttributeMaxDynamicSharedMemorySize, SMEM_TOTAL);

    prep_xz_all<<<dim3(64 + NCHUNKS, 16), 256>>>(samples, centers);   // idx 0
    prep_w<<<dim3(NCHUNKS, 2), 256>>>(weight);                        // idx 1
    prep_sq<<<NSAMP + NCHUNKS * 128, 128>>>(samples, centers);        // idx 2
    laplace_main<<<dim3(64, 2), 256, SMEM_TOTAL>>>();                 // idx 3 (ncu target)
    reduce2<<<(NSAMP * YDIM) / 512, 128>>>(out);                      // idx 4
}

// round 12
// speedup vs baseline: 1.1453x; 1.1453x over previous
#include <cuda_runtime.h>
#include <cuda_fp16.h>
#include <stdint.h>

#define NSAMP 8192
#define NCENT 10000
#define XDIM  1024
#define YDIM  128
#define NCHUNKS 79

// ---------------- device scratch ----------------
__device__ __align__(16) __half g_xt[(size_t)64 * 16 * 8192];
__device__ __align__(16) __half g_zt[(size_t)NCHUNKS * 16 * 8192];
__device__ __align__(16) __half g_wt[(size_t)NCHUNKS * 16384];
__device__ float g_xsq[NSAMP];
__device__ float g_zsq[NCHUNKS * 128];
__device__ float g_part[(size_t)2 * NSAMP * YDIM];

// smem: 4 stages x 32KB, W 2x32KB, K 32KB, zsq 2x512B
static constexpr int OFF_W  = 131072;
static constexpr int OFF_K  = 196608;
static constexpr int OFF_ZQ = 229376;
static constexpr int SMEM_TOTAL = 230400;

// ---------------- helpers ----------------
__device__ __forceinline__ uint32_t smem_u32(const void* p) {
    uint32_t a;
    asm("{ .reg .u64 t; cvta.to.shared.u64 t, %1; cvt.u32.u64 %0, t; }" : "=r"(a) : "l"(p));
    return a;
}
#define CP_ASYNC16(dst, src) \
    asm volatile("cp.async.cg.shared.global [%0], [%1], 16;" :: "r"(dst), "l"(src) : "memory")
#define CP_COMMIT() asm volatile("cp.async.commit_group;" ::: "memory")
template <int N> __device__ __forceinline__ void cp_wait() {
    asm volatile("cp.async.wait_group %0;" :: "n"(N) : "memory");
}

__device__ __forceinline__ uint32_t tile_off(int r, int c) {
    return (uint32_t)(r * 128 + (((c >> 3) ^ (r & 7)) << 4) + ((c & 7) << 1));
}
__device__ __forceinline__ uint32_t lds_addr(uint32_t base, int r0, int c8b, int lane) {
    int r = r0 + (lane & 15);
    int c8 = c8b + ((lane >> 4) & 1);
    return base + r * 128 + ((c8 ^ (r & 7)) << 4);
}
__device__ __forceinline__ void ldsm4(uint32_t a, uint32_t& r0, uint32_t& r1, uint32_t& r2, uint32_t& r3) {
    asm volatile("ldmatrix.sync.aligned.m8n8.x4.shared.b16 {%0,%1,%2,%3}, [%4];"
                 : "=r"(r0), "=r"(r1), "=r"(r2), "=r"(r3) : "r"(a));
}
__device__ __forceinline__ void ldsm4t(uint32_t a, uint32_t& r0, uint32_t& r1, uint32_t& r2, uint32_t& r3) {
    asm volatile("ldmatrix.sync.aligned.m8n8.x4.trans.shared.b16 {%0,%1,%2,%3}, [%4];"
                 : "=r"(r0), "=r"(r1), "=r"(r2), "=r"(r3) : "r"(a));
}
__device__ __forceinline__ void mma16816(float* c, const uint32_t* a, const uint32_t* b) {
    asm volatile("mma.sync.aligned.m16n8k16.row.col.f32.f16.f16.f32 "
        "{%0,%1,%2,%3}, {%4,%5,%6,%7}, {%8,%9}, {%0,%1,%2,%3};"
        : "+f"(c[0]), "+f"(c[1]), "+f"(c[2]), "+f"(c[3])
        : "r"(a[0]), "r"(a[1]), "r"(a[2]), "r"(a[3]), "r"(b[0]), "r"(b[1]));
}

// ---------------- prep kernels ----------------
__global__ void prep_xz_all(const float* __restrict__ x, const float* __restrict__ z) {
    int blk = blockIdx.x, ks = blockIdx.y, t = threadIdx.x;
    const float* src;
    __half* d;
    int validRows, lblk;
    if (blk < 64) { src = x; d = g_xt; validRows = NSAMP; lblk = blk; }
    else          { src = z; d = g_zt; validRows = NCENT; lblk = blk - 64; }
    d += ((size_t)(lblk * 16 + ks)) * 8192;
    #pragma unroll
    for (int it = 0; it < 4; ++it) {
        int id = it * 256 + t;
        int r = id >> 3, c8 = id & 7;
        int gr = lblk * 128 + r;
        float4 v0 = {0, 0, 0, 0}, v1 = {0, 0, 0, 0};
        if (gr < validRows) {
            const float* p = src + (size_t)gr * XDIM + ks * 64 + c8 * 8;
            v0 = *(const float4*)p;
            v1 = *(const float4*)(p + 4);
        }
        __half2* o = (__half2*)((char*)d + r * 128 + ((c8 ^ (r & 7)) << 4));
        o[0] = __floats2half2_rn(v0.x, v0.y);
        o[1] = __floats2half2_rn(v0.z, v0.w);
        o[2] = __floats2half2_rn(v1.x, v1.y);
        o[3] = __floats2half2_rn(v1.z, v1.w);
    }
}
__global__ void prep_w(const float* __restrict__ w) {
    int chunk = blockIdx.x, sub = blockIdx.y, t = threadIdx.x;
    __half* d = g_wt + (size_t)chunk * 16384 + sub * 8192;
    #pragma unroll
    for (int it = 0; it < 4; ++it) {
        int id = it * 256 + t;
        int r = id >> 3, c8 = id & 7;
        int center = chunk * 128 + r;
        float4 v0 = {0, 0, 0, 0}, v1 = {0, 0, 0, 0};
        if (center < NCENT) {
            const float* p = w + (size_t)center * YDIM + sub * 64 + c8 * 8;
            v0 = *(const float4*)p;
            v1 = *(const float4*)(p + 4);
        }
        __half2* o = (__half2*)((char*)d + r * 128 + ((c8 ^ (r & 7)) << 4));
        o[0] = __floats2half2_rn(v0.x, v0.y);
        o[1] = __floats2half2_rn(v0.z, v0.w);
        o[2] = __floats2half2_rn(v1.x, v1.y);
        o[3] = __floats2half2_rn(v1.z, v1.w);
    }
}
__global__ void prep_sq(const float* __restrict__ x, const float* __restrict__ z) {
    __shared__ float ws[4];
    int r = blockIdx.x, t = threadIdx.x;
    const float* src = nullptr;
    float* dst;
    if (r < NSAMP) { src = x + (size_t)r * XDIM; dst = g_xsq + r; }
    else {
        int zr = r - NSAMP;
        dst = g_zsq + zr;
        if (zr < NCENT) src = z + (size_t)zr * XDIM;
    }
    float s = 0.f;
    if (src) {
        float4 a = ((const float4*)src)[t];
        float4 b = ((const float4*)src)[t + 128];
        s = a.x * a.x;
        s = fmaf(a.y, a.y, s); s = fmaf(a.z, a.z, s); s = fmaf(a.w, a.w, s);
        s = fmaf(b.x, b.x, s); s = fmaf(b.y, b.y, s);
        s = fmaf(b.z, b.z, s); s = fmaf(b.w, b.w, s);
    }
    for (int o = 16; o; o >>= 1) s += __shfl_down_sync(0xffffffffu, s, o);
    if ((t & 31) == 0) ws[t >> 5] = s;
    __syncthreads();
    if (t == 0) dst[0] = ws[0] + ws[1] + ws[2] + ws[3];
}
__global__ void reduce2(float* __restrict__ out) {
    int i = blockIdx.x * 128 + threadIdx.x;
    const float4* p = (const float4*)g_part;
    float4 a = p[i], b = p[i + (NSAMP * YDIM) / 4];
    ((float4*)out)[i] = make_float4(a.x + b.x, a.y + b.y, a.z + b.z, a.w + b.w);
}

// ---------------- main kernel (512 threads, 16 warps 4x4, 2-kstep windows) ----
// one stage fill (X 16KB | Z 16KB), no commit
__device__ __forceinline__ void fill_stage(uint32_t sb, int s, const char* x, const char* z, int tid) {
    uint32_t dst = sb + (uint32_t)s * 32768;
    #pragma unroll
    for (int i = 0; i < 2; ++i) CP_ASYNC16(dst + (i * 512 + tid) * 16, x + (i * 512 + tid) * 16);
    #pragma unroll
    for (int i = 0; i < 2; ++i) CP_ASYNC16(dst + 16384 + (i * 512 + tid) * 16, z + (i * 512 + tid) * 16);
}
__device__ __forceinline__ void load_wq(uint32_t sb, int c, int tid) {
    const char* wg = (const char*)(g_wt + (size_t)c * 16384);
    uint32_t wdst = sb + OFF_W + (uint32_t)(c & 1) * 32768;
    #pragma unroll
    for (int i = 0; i < 4; ++i) CP_ASYNC16(wdst + (i * 512 + tid) * 16, wg + (i * 512 + tid) * 16);
    if (tid < 32)
        CP_ASYNC16(sb + OFF_ZQ + (uint32_t)(c & 1) * 512 + tid * 16,
                   (const char*)(g_zsq + c * 128) + tid * 16);
    CP_COMMIT();
}

__global__ __launch_bounds__(512, 1) void laplace_main() {
    extern __shared__ char smem[];
    const int tid = threadIdx.x, lane = tid & 31, wid = tid >> 5;
    const int wm = wid >> 2, wn = wid & 3;          // 4 x 4 warp grid, warp tile 32x32
    const int gid = lane >> 2, tig = lane & 3;
    const int mblk = blockIdx.x, grp = blockIdx.y;
    const int c0 = grp ? 40 : 0, c1 = grp ? NCHUNKS : 40;

    uint32_t sb = smem_u32(smem);

    float xsq[4];
    #pragma unroll
    for (int i = 0; i < 2; ++i) {
        xsq[2 * i]     = g_xsq[mblk * 128 + wm * 32 + i * 16 + gid];
        xsq[2 * i + 1] = g_xsq[mblk * 128 + wm * 32 + i * 16 + gid + 8];
    }

    float O[2][4][4];
    #pragma unroll
    for (int i = 0; i < 2; ++i)
        #pragma unroll
        for (int j = 0; j < 4; ++j)
            O[i][j][0] = O[i][j][1] = O[i][j][2] = O[i][j][3] = 0.f;

    const char* xg = (const char*)(g_xt + (size_t)mblk * 16 * 8192);

    // prologue: ksteps 0-3 of chunk c0 (two groups) + W/zsq of c0 (one group)
    {
        const char* zg = (const char*)(g_zt + (size_t)c0 * 16 * 8192);
        fill_stage(sb, 0, xg, zg, tid);
        fill_stage(sb, 1, xg + 16384, zg + 16384, tid);
        CP_COMMIT();
        fill_stage(sb, 2, xg + 2 * 16384, zg + 2 * 16384, tid);
        fill_stage(sb, 3, xg + 3 * 16384, zg + 3 * 16384, tid);
        CP_COMMIT();
        load_wq(sb, c0, tid);
    }

    for (int c = c0; c < c1; ++c) {
        const char* zg  = (const char*)(g_zt + (size_t)c * 16 * 8192);
        const char* zgn = zg + 16 * 16384;   // next chunk: 16 tiles x 16384 BYTES

        float S[2][4][4];
        #pragma unroll
        for (int i = 0; i < 2; ++i)
            #pragma unroll
            for (int j = 0; j < 4; ++j)
                S[i][j][0] = S[i][j][1] = S[i][j][2] = S[i][j][3] = 0.f;

        #pragma unroll 2
        for (int w = 0; w < 8; ++w) {
            cp_wait<0>();        // drains refill group from previous window (+W group)
            __syncthreads();     // stage data visible; stages from last window reusable

            // refill flat ksteps 2w+2, 2w+3 (cross into next chunk at w==7)
            if (!(c == c0 && w == 0) && !(c == c1 - 1 && w == 7)) {
                int r0 = 2 * w + 2;   // 2..16 (even)
                const char* z0 = (r0 >= 16) ? (zgn + (r0 - 16) * 16384) : (zg + r0 * 16384);
                const char* z1 = (r0 + 1 >= 16) ? (zgn + (r0 - 15) * 16384) : (zg + (r0 + 1) * 16384);
                fill_stage(sb, r0 & 3, xg + (r0 & 15) * 16384, z0, tid);
                fill_stage(sb, (r0 + 1) & 3, xg + ((r0 + 1) & 15) * 16384, z1, tid);
                CP_COMMIT();
            }

            // consume ksteps 2w, 2w+1 with no intervening barrier
            #pragma unroll
            for (int ks2 = 0; ks2 < 2; ++ks2) {
                const int ks = 2 * w + ks2;
                uint32_t xb = sb + (uint32_t)(ks & 3) * 32768, zb = xb + 16384;
                #pragma unroll
                for (int k16 = 0; k16 < 4; ++k16) {
                    uint32_t a[2][4], b[4][2];
                    #pragma unroll
                    for (int i = 0; i < 2; ++i)
                        ldsm4(lds_addr(xb, wm * 32 + i * 16, k16 * 2, lane),
                              a[i][0], a[i][1], a[i][2], a[i][3]);
                    #pragma unroll
                    for (int jj = 0; jj < 2; ++jj) {
                        uint32_t r0, r1, r2, r3;
                        ldsm4(lds_addr(zb, wn * 32 + jj * 16, k16 * 2, lane), r0, r1, r2, r3);
                        b[2 * jj][0] = r0; b[2 * jj][1] = r2;
                        b[2 * jj + 1][0] = r1; b[2 * jj + 1][1] = r3;
                    }
                    #pragma unroll
                    for (int i = 0; i < 2; ++i)
                        #pragma unroll
                        for (int j = 0; j < 4; ++j)
                            mma16816(S[i][j], a[i], b[j]);
                }
            }
        }

        // epilogue: S -> k (fp16) -> smem K tile   (W/zsq of c complete: drained at w=0 + syncs)
        const float* zqs = (const float*)(smem + OFF_ZQ + (c & 1) * 512);
        char* kbase = smem + OFF_K + (wn >> 1) * 16384;
        #pragma unroll
        for (int j = 0; j < 4; ++j) {
            int col = wn * 32 + j * 8 + 2 * tig;
            float zq0 = zqs[col], zq1 = zqs[col + 1];
            #pragma unroll
            for (int i = 0; i < 2; ++i) {
                int r = wm * 32 + i * 16 + gid;
                float d2a = fmaxf(fmaf(-2.f, S[i][j][0], xsq[2 * i] + zq0), 1e-12f);
                float d2b = fmaxf(fmaf(-2.f, S[i][j][1], xsq[2 * i] + zq1), 1e-12f);
                float d2c = fmaxf(fmaf(-2.f, S[i][j][2], xsq[2 * i + 1] + zq0), 1e-12f);
                float d2d = fmaxf(fmaf(-2.f, S[i][j][3], xsq[2 * i + 1] + zq1), 1e-12f);
                float k0 = __expf(-0.1f * d2a * __frsqrt_rn(d2a));
                float k1 = __expf(-0.1f * d2b * __frsqrt_rn(d2b));
                float k2 = __expf(-0.1f * d2c * __frsqrt_rn(d2c));
                float k3 = __expf(-0.1f * d2d * __frsqrt_rn(d2d));
                *(__half2*)(kbase + tile_off(r, col & 63))     = __floats2half2_rn(k0, k1);
                *(__half2*)(kbase + tile_off(r + 8, col & 63)) = __floats2half2_rn(k2, k3);
            }
        }
        __syncthreads();    // K handoff; all threads past GEMM2(c-1) reads of W too
        if (c + 1 < c1) load_wq(sb, c + 1, tid);

        // GEMM2: O += K[m][center] * W[center][y]
        uint32_t wbase = sb + OFF_W + (uint32_t)(c & 1) * 32768 + (wn >> 1) * 16384;
        #pragma unroll
        for (int k0 = 0; k0 < 8; ++k0) {
            uint32_t a[2][4], b[4][2];
            #pragma unroll
            for (int i = 0; i < 2; ++i)
                ldsm4(lds_addr(sb + OFF_K + (k0 >> 2) * 16384, wm * 32 + i * 16, (k0 & 3) * 2, lane),
                      a[i][0], a[i][1], a[i][2], a[i][3]);
            #pragma unroll
            for (int jj = 0; jj < 2; ++jj) {
                uint32_t r0, r1, r2, r3;
                ldsm4t(lds_addr(wbase, k0 * 16, (wn & 1) * 4 + jj * 2, lane), r0, r1, r2, r3);
                b[2 * jj][0] = r0; b[2 * jj][1] = r1;
                b[2 * jj + 1][0] = r2; b[2 * jj + 1][1] = r3;
            }
            #pragma unroll
            for (int i = 0; i < 2; ++i)
                #pragma unroll
                for (int j = 0; j < 4; ++j)
                    mma16816(O[i][j], a[i], b[j]);
        }
        // no trailing sync: next K write is after 8 window syncs of next chunk
    }

    // writeout partials
    float* pout = g_part + (size_t)grp * NSAMP * YDIM;
    #pragma unroll
    for (int i = 0; i < 2; ++i)
        #pragma unroll
        for (int j = 0; j < 4; ++j) {
            int r = mblk * 128 + wm * 32 + i * 16 + gid;
            int col = wn * 32 + j * 8 + 2 * tig;
            *(float2*)&pout[(size_t)r * YDIM + col] = make_float2(O[i][j][0], O[i][j][1]);
            *(float2*)&pout[(size_t)(r + 8) * YDIM + col] = make_float2(O[i][j][2], O[i][j][3]);
        }
}

// ---------------- launch ----------------
extern "C" void kernel_launch(void* const* d_in, const int* in_sizes, int n_in,
                              void* d_out, int out_size) {
    const float* samples = (const float*)d_in[0];
    const float* centers = (const float*)d_in[1];
    const float* weight  = (const float*)d_in[2];
    float* out = (float*)d_out;

    cudaFuncSetAttribute(laplace_main, cudaFuncAttributeMaxDynamicSharedMemorySize, SMEM_TOTAL);

    prep_xz_all<<<dim3(64 + NCHUNKS, 16), 256>>>(samples, centers);   // idx 0
    prep_w<<<dim3(NCHUNKS, 2), 256>>>(weight);                        // idx 1
    prep_sq<<<NSAMP + NCHUNKS * 128, 128>>>(samples, centers);        // idx 2
    laplace_main<<<dim3(64, 2), 512, SMEM_TOTAL>>>();                 // idx 3 (ncu target)
    reduce2<<<(NSAMP * YDIM) / 512, 128>>>(out);                      // idx 4
}